// round 12
// baseline (speedup 1.0000x reference)
#include <cuda_runtime.h>

#define B_ 4096
#define N_ 64
#define H_ 256
#define M_ 320          // 256 W-rows + 64 (h+w)-rows

typedef unsigned long long u64;

// Scratch (allocation-free rule: __device__ globals)
__device__ float g_UV[N_ * H_];     //  64 KiB
__device__ float g_Mt[H_ * M_];     // 320 KiB  Mt[k][m] = W[m][k] (m<256) | h+w (m>=256)

// ---------- packed fp32x2 helpers (sm_103a FFMA2) ----------
__device__ __forceinline__ u64 pack2(float x, float y) {
    u64 r; asm("mov.b64 %0, {%1, %2};" : "=l"(r) : "f"(x), "f"(y)); return r;
}
__device__ __forceinline__ u64 fma2(u64 a, u64 b, u64 c) {
    u64 d; asm("fma.rn.f32x2 %0, %1, %2, %3;" : "=l"(d) : "l"(a), "l"(b), "l"(c)); return d;
}
__device__ __forceinline__ float2 unpack2(u64 v) {
    float2 r; asm("mov.b64 {%0, %1}, %2;" : "=f"(r.x), "=f"(r.y) : "l"(v)); return r;
}

// ---------------------------------------------------------------------------
// Pre-kernel:
//  blocks [0,2048):    UV[n,k] = sum_h h[n,h]*U[k,h] + w[n,h]*V[k,h]
//  blocks [2048,2068): transpose  Mt[k][m] = M[m][k], M = concat(W, h+w)
//                      20 blocks of 64m x 64k tiles via smem.
// ---------------------------------------------------------------------------
__global__ void __launch_bounds__(256) k_pre(
    const float* __restrict__ h, const float* __restrict__ w,
    const float* __restrict__ U, const float* __restrict__ V,
    const float* __restrict__ W)
{
    const int tid = threadIdx.x;
    const int blk = blockIdx.x;

    if (blk < 2048) {
        // UV: warp per output element
        const int n = blk >> 5;
        const int kg = blk & 31;
        const int warp = tid >> 5;
        const int lane = tid & 31;
        const int k = kg * 8 + warp;
        const int off = lane * 8;

        const float4* u4 = (const float4*)(U + k * H_ + off);
        const float4* v4 = (const float4*)(V + k * H_ + off);
        const float4* h4 = (const float4*)(h + n * H_ + off);
        const float4* w4 = (const float4*)(w + n * H_ + off);
        float4 u0 = u4[0], u1 = u4[1];
        float4 v0 = v4[0], v1 = v4[1];
        float4 x0 = __ldg(h4), x1 = __ldg(h4 + 1);
        float4 y0 = __ldg(w4), y1 = __ldg(w4 + 1);

        float acc = 0.f;
        acc = fmaf(u0.x, x0.x, acc); acc = fmaf(u0.y, x0.y, acc);
        acc = fmaf(u0.z, x0.z, acc); acc = fmaf(u0.w, x0.w, acc);
        acc = fmaf(u1.x, x1.x, acc); acc = fmaf(u1.y, x1.y, acc);
        acc = fmaf(u1.z, x1.z, acc); acc = fmaf(u1.w, x1.w, acc);
        acc = fmaf(v0.x, y0.x, acc); acc = fmaf(v0.y, y0.y, acc);
        acc = fmaf(v0.z, y0.z, acc); acc = fmaf(v0.w, y0.w, acc);
        acc = fmaf(v1.x, y1.x, acc); acc = fmaf(v1.y, y1.y, acc);
        acc = fmaf(v1.z, y1.z, acc); acc = fmaf(v1.w, y1.w, acc);

#pragma unroll
        for (int o = 16; o > 0; o >>= 1)
            acc += __shfl_xor_sync(0xFFFFFFFFu, acc, o);
        if (lane == 0) g_UV[n * H_ + k] = acc;
    } else {
        // transpose tile
        __shared__ float til[64 * 65];
        const int id = blk - 2048;
        const int mt = id % 5;
        const int kt = id / 5;
        const int r = tid >> 2;        // 0..63
        const int q = tid & 3;         // 0..3
        const int m = mt * 64 + r;
        const int k0 = kt * 64;

#pragma unroll
        for (int i = 0; i < 4; ++i) {
            float4 v;
            const int kk = k0 + q * 16 + 4 * i;
            if (m < 256) {
                v = *(const float4*)&W[m * H_ + kk];
            } else {
                const int n = m - 256;
                float4 x = *(const float4*)&h[n * H_ + kk];
                float4 y = *(const float4*)&w[n * H_ + kk];
                v = make_float4(x.x + y.x, x.y + y.y, x.z + y.z, x.w + y.w);
            }
            til[r * 65 + q * 16 + 4 * i + 0] = v.x;
            til[r * 65 + q * 16 + 4 * i + 1] = v.y;
            til[r * 65 + q * 16 + 4 * i + 2] = v.z;
            til[r * 65 + q * 16 + 4 * i + 3] = v.w;
        }
        __syncthreads();
        // write Mt[k0+r][mt*64 + q*16 .. +15]
#pragma unroll
        for (int i = 0; i < 4; ++i) {
            float4 o;
            o.x = til[(q * 16 + 4 * i + 0) * 65 + r];
            o.y = til[(q * 16 + 4 * i + 1) * 65 + r];
            o.z = til[(q * 16 + 4 * i + 2) * 65 + r];
            o.w = til[(q * 16 + 4 * i + 3) * 65 + r];
            *(float4*)&g_Mt[(k0 + r) * M_ + mt * 64 + q * 16 + 4 * i] = o;
        }
    }
}

// ---------------------------------------------------------------------------
// Fused kernel: one block per 16-b tile, all 64 n.
//  Phase A: C[16,320] = s_tile @ Mt  (smem GEMM, FFMA2, 4b x 5m micro)
//           -> sW_s[16][256] (overlay) + gate_s[16][64] = sigmoid (overlay)
//  Phase B: barrier-free streaming: out[b,n,:] = normalize(h + g*prelu(UV+sW))
// dynamic smem: [0,16K) sa/sW_s ; [16K,56K) Mt chunk / gate_s
// ---------------------------------------------------------------------------
__device__ __forceinline__ void row_step(const float4 uv, const float4 hh,
                                         const float4 sw, const float g,
                                         const float a, float4& o, float& ss)
{
    float c, t;
    c = uv.x + sw.x; c = (c >= 0.f) ? c : a * c; t = fmaf(g, c, hh.x); o.x = t; ss = fmaf(t, t, ss);
    c = uv.y + sw.y; c = (c >= 0.f) ? c : a * c; t = fmaf(g, c, hh.y); o.y = t; ss = fmaf(t, t, ss);
    c = uv.z + sw.z; c = (c >= 0.f) ? c : a * c; t = fmaf(g, c, hh.z); o.z = t; ss = fmaf(t, t, ss);
    c = uv.w + sw.w; c = (c >= 0.f) ? c : a * c; t = fmaf(g, c, hh.w); o.w = t; ss = fmaf(t, t, ss);
}

#define SMEM_BYTES 57344

__global__ void __launch_bounds__(256, 2) k_fused(
    const float* __restrict__ s, const float* __restrict__ h,
    const float* __restrict__ a_ptr, float* __restrict__ out)
{
    extern __shared__ float smem[];
    float* sa = smem;           // [16][256] s-tile, later sW_s
    float* mts = smem + 4096;   // [32][320] Mt chunk, later gate_s[16][64]

    const int tid = threadIdx.x;
    const int b0 = blockIdx.x * 16;

    // ---- stage s-tile [16][256] row-major (coalesced, conflict-free) ----
    {
        const int r = tid >> 4;
        const int ks = (tid & 15) << 4;
        const float4* src = (const float4*)&s[(b0 + r) * H_ + ks];
        float4* dst = (float4*)&sa[r * 256 + ks];
        dst[0] = src[0]; dst[1] = src[1]; dst[2] = src[2]; dst[3] = src[3];
    }

    // ---- Phase A: GEMM ----
    const int ty = tid >> 6;       // 0..3
    const int tx = tid & 63;       // 0..63
    const int rb = ty << 2;        // 4 b-rows

    u64 acc[2][5] = {};

    for (int kc = 0; kc < H_; kc += 32) {
        __syncthreads();
        // stage Mt chunk [32][320]
        {
            const int kr = tid >> 3;
            const int mb = (tid & 7) << 2;
#pragma unroll
            for (int i = 0; i < 10; ++i)
                *(float4*)&mts[kr * M_ + mb + 32 * i] =
                    *(const float4*)&g_Mt[(kc + kr) * M_ + mb + 32 * i];
        }
        __syncthreads();

#pragma unroll 2
        for (int k4 = 0; k4 < 32; k4 += 4) {
            float ar[4][4];
            *(float4*)ar[0] = *(const float4*)&sa[(rb + 0) * 256 + kc + k4];
            *(float4*)ar[1] = *(const float4*)&sa[(rb + 1) * 256 + kc + k4];
            *(float4*)ar[2] = *(const float4*)&sa[(rb + 2) * 256 + kc + k4];
            *(float4*)ar[3] = *(const float4*)&sa[(rb + 3) * 256 + kc + k4];
#pragma unroll
            for (int kk = 0; kk < 4; ++kk) {
                const u64 ap01 = pack2(ar[0][kk], ar[1][kk]);
                const u64 ap23 = pack2(ar[2][kk], ar[3][kk]);
                const float* mrow = &mts[(k4 + kk) * M_ + tx];
#pragma unroll
                for (int j = 0; j < 5; ++j) {
                    const float mv = mrow[64 * j];
                    const u64 md = pack2(mv, mv);
                    acc[0][j] = fma2(ap01, md, acc[0][j]);
                    acc[1][j] = fma2(ap23, md, acc[1][j]);
                }
            }
        }
    }

    __syncthreads();   // all sa reads done; safe to overlay

    // ---- write sW_s / gate_s ----
#pragma unroll
    for (int j = 0; j < 5; ++j) {
        const int m = tx + 64 * j;
        const float2 p0 = unpack2(acc[0][j]);   // b rb+0, rb+1
        const float2 p1 = unpack2(acc[1][j]);   // b rb+2, rb+3
        if (m < 256) {
            sa[(rb + 0) * 256 + m] = p0.x;
            sa[(rb + 1) * 256 + m] = p0.y;
            sa[(rb + 2) * 256 + m] = p1.x;
            sa[(rb + 3) * 256 + m] = p1.y;
        } else {
            const int n = m - 256;
            mts[(rb + 0) * 64 + n] = 1.0f / (1.0f + __expf(-p0.x));
            mts[(rb + 1) * 64 + n] = 1.0f / (1.0f + __expf(-p0.y));
            mts[(rb + 2) * 64 + n] = 1.0f / (1.0f + __expf(-p1.x));
            mts[(rb + 3) * 64 + n] = 1.0f / (1.0f + __expf(-p1.y));
        }
    }
    __syncthreads();

    // ---- Phase B: streaming (no further barriers) ----
    const int warp = tid >> 5;
    const int lane = tid & 31;
    const int k0f = lane * 4;
    const int k1f = 128 + lane * 4;
    const float a = __ldg(a_ptr);

    for (int b = 0; b < 16; ++b) {
        const float4 s0 = *(const float4*)&sa[b * 256 + k0f];
        const float4 s1 = *(const float4*)&sa[b * 256 + k1f];
        const size_t ob = (size_t)(b0 + b) * (N_ * H_);
#pragma unroll
        for (int t8 = 0; t8 < 8; ++t8) {
            const int n = warp + 8 * t8;
            const float g = mts[b * 64 + n];
            const float4 uv0 = *(const float4*)&g_UV[n * H_ + k0f];
            const float4 uv1 = *(const float4*)&g_UV[n * H_ + k1f];
            const float4 h0 = __ldg((const float4*)&h[n * H_ + k0f]);
            const float4 h1 = __ldg((const float4*)&h[n * H_ + k1f]);

            float ss = 0.f;
            float4 o0, o1;
            row_step(uv0, h0, s0, g, a, o0, ss);
            row_step(uv1, h1, s1, g, a, o1, ss);

#pragma unroll
            for (int o = 16; o > 0; o >>= 1)
                ss += __shfl_xor_sync(0xFFFFFFFFu, ss, o);
            const float inv = rsqrtf(ss);

            *(float4*)&out[ob + n * H_ + k0f] =
                make_float4(o0.x * inv, o0.y * inv, o0.z * inv, o0.w * inv);
            *(float4*)&out[ob + n * H_ + k1f] =
                make_float4(o1.x * inv, o1.y * inv, o1.z * inv, o1.w * inv);
        }
    }
}

// ---------------------------------------------------------------------------
extern "C" void kernel_launch(void* const* d_in, const int* in_sizes, int n_in,
                              void* d_out, int out_size)
{
    const float* s_t = (const float*)d_in[0];   // [B,H]
    const float* h   = (const float*)d_in[1];   // [1,N,H]
    const float* w   = (const float*)d_in[2];   // [1,N,H]
    const float* U   = (const float*)d_in[3];   // [H,H]
    const float* V   = (const float*)d_in[4];   // [H,H]
    const float* W   = (const float*)d_in[5];   // [H,H]
    const float* pa  = (const float*)d_in[6];   // [1]
    float* out = (float*)d_out;                 // [B,N,H]

    static bool init = false;
    if (!init) {
        cudaFuncSetAttribute(k_fused,
            cudaFuncAttributeMaxDynamicSharedMemorySize, SMEM_BYTES);
        init = true;
    }

    k_pre<<<2048 + 20, 256>>>(h, w, U, V, W);
    k_fused<<<B_ / 16, 256, SMEM_BYTES>>>(s_t, h, pa, out);
}

// round 13
// speedup vs baseline: 1.0915x; 1.0915x over previous
#include <cuda_runtime.h>

#define B_ 4096
#define N_ 64
#define H_ 256
#define TB3 16

#define NB_GEMM 320   // 64 b-tiles x 5 m-tiles (64x64 tiles, K=256)
#define NB_UV   2048

typedef unsigned long long u64;

// Scratch (allocation-free rule: __device__ globals)
__device__ float g_UV[N_ * H_];     //  64 KiB
__device__ float g_sW[B_ * H_];     //   4 MiB
__device__ float g_gate[B_ * N_];   //   1 MiB

// ---------- packed fp32x2 helpers (sm_103a FFMA2) ----------
__device__ __forceinline__ u64 pack2(float x, float y) {
    u64 r; asm("mov.b64 %0, {%1, %2};" : "=l"(r) : "f"(x), "f"(y)); return r;
}
__device__ __forceinline__ u64 fma2(u64 a, u64 b, u64 c) {
    u64 d; asm("fma.rn.f32x2 %0, %1, %2, %3;" : "=l"(d) : "l"(a), "l"(b), "l"(c)); return d;
}
__device__ __forceinline__ float2 unpack2(u64 v) {
    float2 r; asm("mov.b64 {%0, %1}, %2;" : "=f"(r.x), "=f"(r.y) : "l"(v)); return r;
}

// ---------------------------------------------------------------------------
// Merged kernel 1+2 — R3's exact measured-best GEMM config (k12 ~31us):
//  blocks [0,320):    GEMM  C[b,m] = s_t[b,:].M[m,:], M = concat(W_w, h+w)
//    64x64 tiles, Kc=32, k-major smem, 4b x 4m micro via f32x2 packed FMA
//    (pack-in-loop).  m<256 -> g_sW ; gate tile (mx==4) -> g_gate = sigmoid
//  blocks [320,2368): UV[n,k] = sum_h h[n,h]*U[k,h] + w[n,h]*V[k,h]
// ---------------------------------------------------------------------------
__global__ void __launch_bounds__(256) k12(
    const float* __restrict__ s, const float* __restrict__ W,
    const float* __restrict__ h, const float* __restrict__ w,
    const float* __restrict__ U, const float* __restrict__ V)
{
    __shared__ float sa[32][64];   // [k][b_local]
    __shared__ float sb[32][64];   // [k][m_local]
    const int tid = threadIdx.x;
    const int blk = blockIdx.x;

    if (blk < NB_GEMM) {
        const int mx = blk % 5;
        const int b0 = (blk / 5) * 64;
        const int m0 = mx * 64;
        const bool gate_tile = (mx == 4);
        const int row = tid & 63;
        const int kq = (tid >> 6) << 2;    // 0,4,8,12
        const int tx = tid & 15;
        const int ty = tid >> 4;
        const int rb = ty << 2;
        const int cm = tx << 2;

        u64 acc2[2][4] = {};

        float4 ra0, ra1, rb0, rb1;
        ra0 = *(const float4*)&s[(b0 + row) * H_ + kq];
        ra1 = *(const float4*)&s[(b0 + row) * H_ + 16 + kq];
        if (!gate_tile) {
            rb0 = *(const float4*)&W[(m0 + row) * H_ + kq];
            rb1 = *(const float4*)&W[(m0 + row) * H_ + 16 + kq];
        } else {
            float4 x0 = *(const float4*)&h[row * H_ + kq];
            float4 x1 = *(const float4*)&h[row * H_ + 16 + kq];
            float4 y0 = *(const float4*)&w[row * H_ + kq];
            float4 y1 = *(const float4*)&w[row * H_ + 16 + kq];
            rb0 = make_float4(x0.x + y0.x, x0.y + y0.y, x0.z + y0.z, x0.w + y0.w);
            rb1 = make_float4(x1.x + y1.x, x1.y + y1.y, x1.z + y1.z, x1.w + y1.w);
        }

        for (int kc = 0; kc < H_; kc += 32) {
            sa[kq + 0][row] = ra0.x; sa[kq + 1][row] = ra0.y;
            sa[kq + 2][row] = ra0.z; sa[kq + 3][row] = ra0.w;
            sa[16 + kq + 0][row] = ra1.x; sa[16 + kq + 1][row] = ra1.y;
            sa[16 + kq + 2][row] = ra1.z; sa[16 + kq + 3][row] = ra1.w;
            sb[kq + 0][row] = rb0.x; sb[kq + 1][row] = rb0.y;
            sb[kq + 2][row] = rb0.z; sb[kq + 3][row] = rb0.w;
            sb[16 + kq + 0][row] = rb1.x; sb[16 + kq + 1][row] = rb1.y;
            sb[16 + kq + 2][row] = rb1.z; sb[16 + kq + 3][row] = rb1.w;
            __syncthreads();

            if (kc + 32 < H_) {
                const int kn = kc + 32;
                ra0 = *(const float4*)&s[(b0 + row) * H_ + kn + kq];
                ra1 = *(const float4*)&s[(b0 + row) * H_ + kn + 16 + kq];
                if (!gate_tile) {
                    rb0 = *(const float4*)&W[(m0 + row) * H_ + kn + kq];
                    rb1 = *(const float4*)&W[(m0 + row) * H_ + kn + 16 + kq];
                } else {
                    float4 x0 = *(const float4*)&h[row * H_ + kn + kq];
                    float4 x1 = *(const float4*)&h[row * H_ + kn + 16 + kq];
                    float4 y0 = *(const float4*)&w[row * H_ + kn + kq];
                    float4 y1 = *(const float4*)&w[row * H_ + kn + 16 + kq];
                    rb0 = make_float4(x0.x + y0.x, x0.y + y0.y, x0.z + y0.z, x0.w + y0.w);
                    rb1 = make_float4(x1.x + y1.x, x1.y + y1.y, x1.z + y1.z, x1.w + y1.w);
                }
            }

#pragma unroll 8
            for (int k = 0; k < 32; ++k) {
                const ulonglong2 a2 = *(const ulonglong2*)&sa[k][rb];
                const float4 bv = *(const float4*)&sb[k][cm];
                u64 bx = pack2(bv.x, bv.x);
                u64 by = pack2(bv.y, bv.y);
                u64 bz = pack2(bv.z, bv.z);
                u64 bw = pack2(bv.w, bv.w);
                acc2[0][0] = fma2(a2.x, bx, acc2[0][0]);
                acc2[0][1] = fma2(a2.x, by, acc2[0][1]);
                acc2[0][2] = fma2(a2.x, bz, acc2[0][2]);
                acc2[0][3] = fma2(a2.x, bw, acc2[0][3]);
                acc2[1][0] = fma2(a2.y, bx, acc2[1][0]);
                acc2[1][1] = fma2(a2.y, by, acc2[1][1]);
                acc2[1][2] = fma2(a2.y, bz, acc2[1][2]);
                acc2[1][3] = fma2(a2.y, bw, acc2[1][3]);
            }
            __syncthreads();
        }

#pragma unroll
        for (int ib = 0; ib < 2; ++ib) {
            float2 c0 = unpack2(acc2[ib][0]);
            float2 c1 = unpack2(acc2[ib][1]);
            float2 c2 = unpack2(acc2[ib][2]);
            float2 c3 = unpack2(acc2[ib][3]);
            const int bA = b0 + rb + 2 * ib;
            if (!gate_tile) {
                *(float4*)&g_sW[bA * H_ + m0 + cm] = make_float4(c0.x, c1.x, c2.x, c3.x);
                *(float4*)&g_sW[(bA + 1) * H_ + m0 + cm] = make_float4(c0.y, c1.y, c2.y, c3.y);
            } else {
                *(float4*)&g_gate[bA * N_ + cm] = make_float4(
                    1.0f / (1.0f + __expf(-c0.x)), 1.0f / (1.0f + __expf(-c1.x)),
                    1.0f / (1.0f + __expf(-c2.x)), 1.0f / (1.0f + __expf(-c3.x)));
                *(float4*)&g_gate[(bA + 1) * N_ + cm] = make_float4(
                    1.0f / (1.0f + __expf(-c0.y)), 1.0f / (1.0f + __expf(-c1.y)),
                    1.0f / (1.0f + __expf(-c2.y)), 1.0f / (1.0f + __expf(-c3.y)));
            }
        }
    } else {
        // ---------------- UV part: warp per output element ----------------
        const int id = blk - NB_GEMM;
        const int n = id >> 5;
        const int kg = id & 31;
        const int warp = tid >> 5;
        const int lane = tid & 31;
        const int k = kg * 8 + warp;
        const int off = lane * 8;

        const float4* u4 = (const float4*)(U + k * H_ + off);
        const float4* v4 = (const float4*)(V + k * H_ + off);
        const float4* h4 = (const float4*)(h + n * H_ + off);
        const float4* w4 = (const float4*)(w + n * H_ + off);
        float4 u0 = u4[0], u1 = u4[1];
        float4 v0 = v4[0], v1 = v4[1];
        float4 x0 = __ldg(h4), x1 = __ldg(h4 + 1);
        float4 y0 = __ldg(w4), y1 = __ldg(w4 + 1);

        float acc = 0.f;
        acc = fmaf(u0.x, x0.x, acc); acc = fmaf(u0.y, x0.y, acc);
        acc = fmaf(u0.z, x0.z, acc); acc = fmaf(u0.w, x0.w, acc);
        acc = fmaf(u1.x, x1.x, acc); acc = fmaf(u1.y, x1.y, acc);
        acc = fmaf(u1.z, x1.z, acc); acc = fmaf(u1.w, x1.w, acc);
        acc = fmaf(v0.x, y0.x, acc); acc = fmaf(v0.y, y0.y, acc);
        acc = fmaf(v0.z, y0.z, acc); acc = fmaf(v0.w, y0.w, acc);
        acc = fmaf(v1.x, y1.x, acc); acc = fmaf(v1.y, y1.y, acc);
        acc = fmaf(v1.z, y1.z, acc); acc = fmaf(v1.w, y1.w, acc);

#pragma unroll
        for (int offm = 16; offm > 0; offm >>= 1)
            acc += __shfl_xor_sync(0xFFFFFFFFu, acc, offm);
        if (lane == 0) g_UV[n * H_ + k] = acc;
    }

    // PDL: signal dependents once this block's results are globally visible.
    __threadfence();
    asm volatile("griddepcontrol.launch_dependents;");
}

// ---------------------------------------------------------------------------
// Kernel 3 — R2's exact measured-best body (48.9us): one warp per (b,n) row
// pair; sW+gate staged in smem, double-buffered prefetch; TB3=16.
// PDL: h loads (pure input) pre-wait; producer-written data post-wait.
// grid = (4 n-tiles, B/TB3), block = 256 (warp w -> rows w, w+8)
// ---------------------------------------------------------------------------
__device__ __forceinline__ void row_step(const float4 uv, const float4 hh,
                                         const float4 sw, const float g,
                                         const float a, float4& o, float& ss)
{
    float c, t;
    c = uv.x + sw.x; c = (c >= 0.f) ? c : a * c; t = fmaf(g, c, hh.x); o.x = t; ss = fmaf(t, t, ss);
    c = uv.y + sw.y; c = (c >= 0.f) ? c : a * c; t = fmaf(g, c, hh.y); o.y = t; ss = fmaf(t, t, ss);
    c = uv.z + sw.z; c = (c >= 0.f) ? c : a * c; t = fmaf(g, c, hh.z); o.z = t; ss = fmaf(t, t, ss);
    c = uv.w + sw.w; c = (c >= 0.f) ? c : a * c; t = fmaf(g, c, hh.w); o.w = t; ss = fmaf(t, t, ss);
}

__global__ void __launch_bounds__(256) k3_main(
    const float* __restrict__ h, const float* __restrict__ a_ptr,
    float* __restrict__ out)
{
    __shared__ float4 sw[2][64];
    __shared__ float gt[2][16];

    const int tid = threadIdx.x;
    const int warp = tid >> 5;
    const int lane = tid & 31;
    const int n0 = blockIdx.x * 16;
    const int b0 = blockIdx.y * TB3;

    const int nA = n0 + warp;
    const int nB = n0 + warp + 8;
    const int k0 = lane * 4;
    const int k1 = 128 + lane * 4;

    // h and prelu_a are pure inputs: load before the PDL wait.
    float4 hA0 = __ldg((const float4*)&h[nA * H_ + k0]);
    float4 hA1 = __ldg((const float4*)&h[nA * H_ + k1]);
    float4 hB0 = __ldg((const float4*)&h[nB * H_ + k0]);
    float4 hB1 = __ldg((const float4*)&h[nB * H_ + k1]);
    const float a = __ldg(a_ptr);

    asm volatile("griddepcontrol.wait;");

    float4 uvA0 = *(const float4*)&g_UV[nA * H_ + k0];
    float4 uvA1 = *(const float4*)&g_UV[nA * H_ + k1];
    float4 uvB0 = *(const float4*)&g_UV[nB * H_ + k0];
    float4 uvB1 = *(const float4*)&g_UV[nB * H_ + k1];

    if (tid < 64) sw[0][tid] = __ldg((const float4*)&g_sW[(size_t)b0 * H_] + tid);
    else if (tid < 80) gt[0][tid - 64] = __ldg(&g_gate[b0 * N_ + n0 + (tid - 64)]);
    __syncthreads();

    for (int i = 0; i < TB3; ++i) {
        const int buf = i & 1;
        if (i + 1 < TB3) {
            const int bn = b0 + i + 1;
            if (tid < 64) sw[buf ^ 1][tid] = __ldg((const float4*)&g_sW[(size_t)bn * H_] + tid);
            else if (tid < 80) gt[buf ^ 1][tid - 64] = __ldg(&g_gate[bn * N_ + n0 + (tid - 64)]);
        }

        const float4 s0 = sw[buf][lane];
        const float4 s1 = sw[buf][lane + 32];
        const float gA = gt[buf][warp];
        const float gB = gt[buf][warp + 8];

        float4 oA0, oA1, oB0, oB1;
        float ssA = 0.f, ssB = 0.f;
        row_step(uvA0, hA0, s0, gA, a, oA0, ssA);
        row_step(uvA1, hA1, s1, gA, a, oA1, ssA);
        row_step(uvB0, hB0, s0, gB, a, oB0, ssB);
        row_step(uvB1, hB1, s1, gB, a, oB1, ssB);

#pragma unroll
        for (int offm = 16; offm > 0; offm >>= 1) {
            ssA += __shfl_xor_sync(0xFFFFFFFFu, ssA, offm);
            ssB += __shfl_xor_sync(0xFFFFFFFFu, ssB, offm);
        }
        const float iA = rsqrtf(ssA);
        const float iB = rsqrtf(ssB);

        const int b = b0 + i;
        float4* oA = (float4*)&out[((size_t)b * N_ + nA) * H_];
        float4* oB = (float4*)&out[((size_t)b * N_ + nB) * H_];
        oA[lane]      = make_float4(oA0.x * iA, oA0.y * iA, oA0.z * iA, oA0.w * iA);
        oA[32 + lane] = make_float4(oA1.x * iA, oA1.y * iA, oA1.z * iA, oA1.w * iA);
        oB[lane]      = make_float4(oB0.x * iB, oB0.y * iB, oB0.z * iB, oB0.w * iB);
        oB[32 + lane] = make_float4(oB1.x * iB, oB1.y * iB, oB1.z * iB, oB1.w * iB);

        __syncthreads();
    }
}

// ---------------------------------------------------------------------------
extern "C" void kernel_launch(void* const* d_in, const int* in_sizes, int n_in,
                              void* d_out, int out_size)
{
    const float* s_t = (const float*)d_in[0];   // [B,H]
    const float* h   = (const float*)d_in[1];   // [1,N,H]
    const float* w   = (const float*)d_in[2];   // [1,N,H]
    const float* U   = (const float*)d_in[3];   // [H,H]
    const float* V   = (const float*)d_in[4];   // [H,H]
    const float* W   = (const float*)d_in[5];   // [H,H]
    const float* pa  = (const float*)d_in[6];   // [1]
    float* out = (float*)d_out;                 // [B,N,H]

    k12<<<NB_GEMM + NB_UV, 256>>>(s_t, W, h, w, U, V);

    // k3 with Programmatic Dependent Launch: prologue overlaps k12's tail.
    cudaLaunchConfig_t cfg = {};
    cfg.gridDim = dim3(N_ / 16, B_ / TB3);
    cfg.blockDim = dim3(256);
    cfg.dynamicSmemBytes = 0;
    cfg.stream = 0;
    cudaLaunchAttribute attrs[1];
    attrs[0].id = cudaLaunchAttributeProgrammaticStreamSerialization;
    attrs[0].val.programmaticStreamSerializationAllowed = 1;
    cfg.attrs = attrs;
    cfg.numAttrs = 1;
    cudaLaunchKernelEx(&cfg, k3_main, h, pa, (float*)out);
}

// round 14
// speedup vs baseline: 1.1478x; 1.0516x over previous
#include <cuda_runtime.h>

#define B_ 4096
#define N_ 64
#define H_ 256
#define TB3 16

#define NB_GEMM 320   // 64 b-tiles x 5 m-tiles (64x64 tiles, K=256)
#define NB_UV   2048

// Scratch (allocation-free rule: __device__ globals)
__device__ float g_UV[N_ * H_];     //  64 KiB
__device__ float g_sW[B_ * H_];     //   4 MiB
__device__ float g_gate[B_ * N_];   //   1 MiB

// ---------- tf32 helpers ----------
__device__ __forceinline__ unsigned f2tf32(float x) {
    unsigned r; asm("cvt.rna.tf32.f32 %0, %1;" : "=r"(r) : "f"(x)); return r;
}
// d += A(16x8 tf32) * B(8x8 tf32), row.col, f32 accum
__device__ __forceinline__ void mma8(float& d0, float& d1, float& d2, float& d3,
                                     unsigned a0, unsigned a1, unsigned a2, unsigned a3,
                                     unsigned b0, unsigned b1) {
    asm("mma.sync.aligned.m16n8k8.row.col.f32.tf32.tf32.f32 "
        "{%0,%1,%2,%3}, {%4,%5,%6,%7}, {%8,%9}, {%0,%1,%2,%3};"
        : "+f"(d0), "+f"(d1), "+f"(d2), "+f"(d3)
        : "r"(a0), "r"(a1), "r"(a2), "r"(a3), "r"(b0), "r"(b1));
}

// split 8 floats into tf32 hi/lo and store as 4x uint4 (16B-aligned)
__device__ __forceinline__ void cvt_split8(const float* v, unsigned* hi_dst, unsigned* lo_dst) {
    unsigned h[8], l[8];
#pragma unroll
    for (int i = 0; i < 8; ++i) {
        h[i] = f2tf32(v[i]);
        l[i] = f2tf32(v[i] - __uint_as_float(h[i]));
    }
    *(uint4*)(hi_dst + 0) = make_uint4(h[0], h[1], h[2], h[3]);
    *(uint4*)(hi_dst + 4) = make_uint4(h[4], h[5], h[6], h[7]);
    *(uint4*)(lo_dst + 0) = make_uint4(l[0], l[1], l[2], l[3]);
    *(uint4*)(lo_dst + 4) = make_uint4(l[4], l[5], l[6], l[7]);
}

// ---------------------------------------------------------------------------
// Merged kernel 1+2:
//  blocks [0,320):  GEMM  C[b,m] = s_t[b,:].M[m,:], M = concat(W_w, h+w)
//    64x64 tile, Kc=32, 3xTF32 mma.sync.m16n8k8 (hi*hi + lo*hi + hi*lo).
//    smem stride 36 -> all fragment LDS bank-conflict-free.
//    m<256 -> g_sW ; gate tile (mx==4) -> g_gate = sigmoid(C)
//  blocks [320,2368): UV[n,k] = sum_h h[n,h]*U[k,h] + w[n,h]*V[k,h]
// ---------------------------------------------------------------------------
__global__ void __launch_bounds__(256) k12(
    const float* __restrict__ s, const float* __restrict__ W,
    const float* __restrict__ h, const float* __restrict__ w,
    const float* __restrict__ U, const float* __restrict__ V)
{
    __shared__ unsigned sAhi[64][36], sAlo[64][36];   // [b][k], pad 36
    __shared__ unsigned sBhi[64][36], sBlo[64][36];   // [m][k], pad 36

    const int tid = threadIdx.x;
    const int blk = blockIdx.x;

    if (blk < NB_GEMM) {
        const int mx = blk % 5;
        const int b0 = (blk / 5) * 64;
        const int m0 = mx * 64;
        const bool gate_tile = (mx == 4);

        const int row = tid & 63;          // staging row (A: b-row, B: m-row)
        const int ks = (tid >> 6) << 3;    // staging k-base: 0,8,16,24
        const int wid = tid >> 5;
        const int lane = tid & 31;
        const int g = lane >> 2;           // 0..7
        const int t = lane & 3;            // 0..3
        const int rbw = (wid >> 2) << 5;   // warp b-base: 0 or 32
        const int cmw = (wid & 3) << 4;    // warp m-base: 0,16,32,48

        float d[2][2][4];
#pragma unroll
        for (int i = 0; i < 2; ++i)
#pragma unroll
            for (int j = 0; j < 2; ++j)
#pragma unroll
                for (int r = 0; r < 4; ++r) d[i][j][r] = 0.f;

        float a8[8], b8[8];
        // prologue loads (kc = 0)
        {
            const float4* pa = (const float4*)&s[(b0 + row) * H_ + ks];
            *(float4*)&a8[0] = pa[0]; *(float4*)&a8[4] = pa[1];
            if (!gate_tile) {
                const float4* pb = (const float4*)&W[(m0 + row) * H_ + ks];
                *(float4*)&b8[0] = pb[0]; *(float4*)&b8[4] = pb[1];
            } else {
                const float4* ph = (const float4*)&h[row * H_ + ks];
                const float4* pw = (const float4*)&w[row * H_ + ks];
                float4 x0 = ph[0], x1 = ph[1], y0 = pw[0], y1 = pw[1];
                b8[0] = x0.x + y0.x; b8[1] = x0.y + y0.y; b8[2] = x0.z + y0.z; b8[3] = x0.w + y0.w;
                b8[4] = x1.x + y1.x; b8[5] = x1.y + y1.y; b8[6] = x1.z + y1.z; b8[7] = x1.w + y1.w;
            }
        }

        for (int kc = 0; kc < H_; kc += 32) {
            cvt_split8(a8, &sAhi[row][ks], &sAlo[row][ks]);
            cvt_split8(b8, &sBhi[row][ks], &sBlo[row][ks]);
            __syncthreads();

            if (kc + 32 < H_) {
                const int kn = kc + 32;
                const float4* pa = (const float4*)&s[(b0 + row) * H_ + kn + ks];
                *(float4*)&a8[0] = pa[0]; *(float4*)&a8[4] = pa[1];
                if (!gate_tile) {
                    const float4* pb = (const float4*)&W[(m0 + row) * H_ + kn + ks];
                    *(float4*)&b8[0] = pb[0]; *(float4*)&b8[4] = pb[1];
                } else {
                    const float4* ph = (const float4*)&h[row * H_ + kn + ks];
                    const float4* pw = (const float4*)&w[row * H_ + kn + ks];
                    float4 x0 = ph[0], x1 = ph[1], y0 = pw[0], y1 = pw[1];
                    b8[0] = x0.x + y0.x; b8[1] = x0.y + y0.y; b8[2] = x0.z + y0.z; b8[3] = x0.w + y0.w;
                    b8[4] = x1.x + y1.x; b8[5] = x1.y + y1.y; b8[6] = x1.z + y1.z; b8[7] = x1.w + y1.w;
                }
            }

#pragma unroll
            for (int kq = 0; kq < 32; kq += 8) {
                // A fragments (bank-conflict-free: bank = 4g+t+const = lane-unique)
                unsigned ah[2][4], al[2][4], bh[2][2], bl[2][2];
#pragma unroll
                for (int bt = 0; bt < 2; ++bt) {
                    const int r0 = rbw + 16 * bt + g;
                    ah[bt][0] = sAhi[r0][kq + t];
                    ah[bt][1] = sAhi[r0 + 8][kq + t];
                    ah[bt][2] = sAhi[r0][kq + t + 4];
                    ah[bt][3] = sAhi[r0 + 8][kq + t + 4];
                    al[bt][0] = sAlo[r0][kq + t];
                    al[bt][1] = sAlo[r0 + 8][kq + t];
                    al[bt][2] = sAlo[r0][kq + t + 4];
                    al[bt][3] = sAlo[r0 + 8][kq + t + 4];
                }
#pragma unroll
                for (int nt = 0; nt < 2; ++nt) {
                    const int c0 = cmw + 8 * nt + g;
                    bh[nt][0] = sBhi[c0][kq + t];
                    bh[nt][1] = sBhi[c0][kq + t + 4];
                    bl[nt][0] = sBlo[c0][kq + t];
                    bl[nt][1] = sBlo[c0][kq + t + 4];
                }
#pragma unroll
                for (int bt = 0; bt < 2; ++bt)
#pragma unroll
                    for (int nt = 0; nt < 2; ++nt) {
                        float* dd = d[bt][nt];
                        mma8(dd[0], dd[1], dd[2], dd[3],
                             ah[bt][0], ah[bt][1], ah[bt][2], ah[bt][3],
                             bh[nt][0], bh[nt][1]);
                        mma8(dd[0], dd[1], dd[2], dd[3],
                             al[bt][0], al[bt][1], al[bt][2], al[bt][3],
                             bh[nt][0], bh[nt][1]);
                        mma8(dd[0], dd[1], dd[2], dd[3],
                             ah[bt][0], ah[bt][1], ah[bt][2], ah[bt][3],
                             bl[nt][0], bl[nt][1]);
                    }
            }
            __syncthreads();
        }

        // epilogue: c[r] -> (b = base + g + 8*(r>=2), m = 2t + (r&1))
#pragma unroll
        for (int bt = 0; bt < 2; ++bt) {
#pragma unroll
            for (int nt = 0; nt < 2; ++nt) {
#pragma unroll
                for (int r = 0; r < 4; ++r) {
                    const int b = b0 + rbw + 16 * bt + g + ((r >> 1) << 3);
                    const int ml = cmw + 8 * nt + 2 * t + (r & 1);
                    const float v = d[bt][nt][r];
                    if (!gate_tile) g_sW[b * H_ + m0 + ml] = v;
                    else g_gate[b * N_ + ml] = 1.0f / (1.0f + __expf(-v));
                }
            }
        }
    } else {
        // ---------------- UV part: warp per output element ----------------
        const int id = blk - NB_GEMM;
        const int n = id >> 5;
        const int kg = id & 31;
        const int warp = tid >> 5;
        const int lane = tid & 31;
        const int k = kg * 8 + warp;
        const int off = lane * 8;

        const float4* u4 = (const float4*)(U + k * H_ + off);
        const float4* v4 = (const float4*)(V + k * H_ + off);
        const float4* h4 = (const float4*)(h + n * H_ + off);
        const float4* w4 = (const float4*)(w + n * H_ + off);
        float4 u0 = u4[0], u1 = u4[1];
        float4 v0 = v4[0], v1 = v4[1];
        float4 x0 = __ldg(h4), x1 = __ldg(h4 + 1);
        float4 y0 = __ldg(w4), y1 = __ldg(w4 + 1);

        float acc = 0.f;
        acc = fmaf(u0.x, x0.x, acc); acc = fmaf(u0.y, x0.y, acc);
        acc = fmaf(u0.z, x0.z, acc); acc = fmaf(u0.w, x0.w, acc);
        acc = fmaf(u1.x, x1.x, acc); acc = fmaf(u1.y, x1.y, acc);
        acc = fmaf(u1.z, x1.z, acc); acc = fmaf(u1.w, x1.w, acc);
        acc = fmaf(v0.x, y0.x, acc); acc = fmaf(v0.y, y0.y, acc);
        acc = fmaf(v0.z, y0.z, acc); acc = fmaf(v0.w, y0.w, acc);
        acc = fmaf(v1.x, y1.x, acc); acc = fmaf(v1.y, y1.y, acc);
        acc = fmaf(v1.z, y1.z, acc); acc = fmaf(v1.w, y1.w, acc);

#pragma unroll
        for (int o = 16; o > 0; o >>= 1)
            acc += __shfl_xor_sync(0xFFFFFFFFu, acc, o);
        if (lane == 0) g_UV[n * H_ + k] = acc;
    }
}

// ---------------------------------------------------------------------------
// Kernel 3 — R2's exact measured-best body: one warp per (b,n) row pair;
// sW+gate staged in smem, double-buffered prefetch; TB3=16.
// grid = (4 n-tiles, B/TB3), block = 256 (warp w -> rows w, w+8)
// ---------------------------------------------------------------------------
__device__ __forceinline__ void row_step(const float4 uv, const float4 hh,
                                         const float4 sw, const float g,
                                         const float a, float4& o, float& ss)
{
    float c, tv;
    c = uv.x + sw.x; c = (c >= 0.f) ? c : a * c; tv = fmaf(g, c, hh.x); o.x = tv; ss = fmaf(tv, tv, ss);
    c = uv.y + sw.y; c = (c >= 0.f) ? c : a * c; tv = fmaf(g, c, hh.y); o.y = tv; ss = fmaf(tv, tv, ss);
    c = uv.z + sw.z; c = (c >= 0.f) ? c : a * c; tv = fmaf(g, c, hh.z); o.z = tv; ss = fmaf(tv, tv, ss);
    c = uv.w + sw.w; c = (c >= 0.f) ? c : a * c; tv = fmaf(g, c, hh.w); o.w = tv; ss = fmaf(tv, tv, ss);
}

__global__ void __launch_bounds__(256) k3_main(
    const float* __restrict__ h, const float* __restrict__ a_ptr,
    float* __restrict__ out)
{
    __shared__ float4 sw[2][64];
    __shared__ float gt[2][16];

    const int tid = threadIdx.x;
    const int warp = tid >> 5;
    const int lane = tid & 31;
    const int n0 = blockIdx.x * 16;
    const int b0 = blockIdx.y * TB3;
    const float a = __ldg(a_ptr);

    const int nA = n0 + warp;
    const int nB = n0 + warp + 8;
    const int k0 = lane * 4;
    const int k1 = 128 + lane * 4;

    float4 uvA0 = *(const float4*)&g_UV[nA * H_ + k0];
    float4 uvA1 = *(const float4*)&g_UV[nA * H_ + k1];
    float4 uvB0 = *(const float4*)&g_UV[nB * H_ + k0];
    float4 uvB1 = *(const float4*)&g_UV[nB * H_ + k1];
    float4 hA0 = __ldg((const float4*)&h[nA * H_ + k0]);
    float4 hA1 = __ldg((const float4*)&h[nA * H_ + k1]);
    float4 hB0 = __ldg((const float4*)&h[nB * H_ + k0]);
    float4 hB1 = __ldg((const float4*)&h[nB * H_ + k1]);

    if (tid < 64) sw[0][tid] = __ldg((const float4*)&g_sW[(size_t)b0 * H_] + tid);
    else if (tid < 80) gt[0][tid - 64] = __ldg(&g_gate[b0 * N_ + n0 + (tid - 64)]);
    __syncthreads();

    for (int i = 0; i < TB3; ++i) {
        const int buf = i & 1;
        if (i + 1 < TB3) {
            const int bn = b0 + i + 1;
            if (tid < 64) sw[buf ^ 1][tid] = __ldg((const float4*)&g_sW[(size_t)bn * H_] + tid);
            else if (tid < 80) gt[buf ^ 1][tid - 64] = __ldg(&g_gate[bn * N_ + n0 + (tid - 64)]);
        }

        const float4 s0 = sw[buf][lane];
        const float4 s1 = sw[buf][lane + 32];
        const float gA = gt[buf][warp];
        const float gB = gt[buf][warp + 8];

        float4 oA0, oA1, oB0, oB1;
        float ssA = 0.f, ssB = 0.f;
        row_step(uvA0, hA0, s0, gA, a, oA0, ssA);
        row_step(uvA1, hA1, s1, gA, a, oA1, ssA);
        row_step(uvB0, hB0, s0, gB, a, oB0, ssB);
        row_step(uvB1, hB1, s1, gB, a, oB1, ssB);

#pragma unroll
        for (int o = 16; o > 0; o >>= 1) {
            ssA += __shfl_xor_sync(0xFFFFFFFFu, ssA, o);
            ssB += __shfl_xor_sync(0xFFFFFFFFu, ssB, o);
        }
        const float iA = rsqrtf(ssA);
        const float iB = rsqrtf(ssB);

        const int b = b0 + i;
        float4* oA = (float4*)&out[((size_t)b * N_ + nA) * H_];
        float4* oB = (float4*)&out[((size_t)b * N_ + nB) * H_];
        oA[lane]      = make_float4(oA0.x * iA, oA0.y * iA, oA0.z * iA, oA0.w * iA);
        oA[32 + lane] = make_float4(oA1.x * iA, oA1.y * iA, oA1.z * iA, oA1.w * iA);
        oB[lane]      = make_float4(oB0.x * iB, oB0.y * iB, oB0.z * iB, oB0.w * iB);
        oB[32 + lane] = make_float4(oB1.x * iB, oB1.y * iB, oB1.z * iB, oB1.w * iB);

        __syncthreads();
    }
}

// ---------------------------------------------------------------------------
extern "C" void kernel_launch(void* const* d_in, const int* in_sizes, int n_in,
                              void* d_out, int out_size)
{
    const float* s_t = (const float*)d_in[0];   // [B,H]
    const float* h   = (const float*)d_in[1];   // [1,N,H]
    const float* w   = (const float*)d_in[2];   // [1,N,H]
    const float* U   = (const float*)d_in[3];   // [H,H]
    const float* V   = (const float*)d_in[4];   // [H,H]
    const float* W   = (const float*)d_in[5];   // [H,H]
    const float* pa  = (const float*)d_in[6];   // [1]
    float* out = (float*)d_out;                 // [B,N,H]

    k12<<<NB_GEMM + NB_UV, 256>>>(s_t, W, h, w, U, V);

    dim3 g3(N_ / 16, B_ / TB3);
    k3_main<<<g3, 256>>>(h, pa, out);
}

// round 15
// speedup vs baseline: 1.1691x; 1.0185x over previous
#include <cuda_runtime.h>

#define B_ 4096
#define N_ 64
#define H_ 256
#define TB3 16

#define NB_GEMM 320   // 64 b-tiles x 5 m-tiles (64x64 tiles, K=256)
#define NB_UV   2048
#define NB_K3   1024

typedef unsigned long long u64;

// Scratch (allocation-free rule: __device__ globals)
__device__ float g_UV[N_ * H_];     //  64 KiB
__device__ float g_sW[B_ * H_];     //   4 MiB
__device__ float g_gate[B_ * N_];   //   1 MiB
__device__ int g_flag_w[64];        // per 64-b tile (5 producer blocks each)
__device__ int g_flag_uv[4];        // per 16-n tile (512 producer blocks each)

// ---------- packed fp32x2 helpers (sm_103a FFMA2) ----------
__device__ __forceinline__ u64 pack2(float x, float y) {
    u64 r; asm("mov.b64 %0, {%1, %2};" : "=l"(r) : "f"(x), "f"(y)); return r;
}
__device__ __forceinline__ u64 fma2(u64 a, u64 b, u64 c) {
    u64 d; asm("fma.rn.f32x2 %0, %1, %2, %3;" : "=l"(d) : "l"(a), "l"(b), "l"(c)); return d;
}
__device__ __forceinline__ float2 unpack2(u64 v) {
    float2 r; asm("mov.b64 {%0, %1}, %2;" : "=f"(r.x), "=f"(r.y) : "l"(v)); return r;
}

__global__ void k_reset() {
    const int t = threadIdx.x;
    if (t < 64) g_flag_w[t] = 0;
    else if (t < 68) g_flag_uv[t - 64] = 0;
}

__device__ __forceinline__ void row_step(const float4 uv, const float4 hh,
                                         const float4 sw, const float g,
                                         const float a, float4& o, float& ss)
{
    float c, t;
    c = uv.x + sw.x; c = (c >= 0.f) ? c : a * c; t = fmaf(g, c, hh.x); o.x = t; ss = fmaf(t, t, ss);
    c = uv.y + sw.y; c = (c >= 0.f) ? c : a * c; t = fmaf(g, c, hh.y); o.y = t; ss = fmaf(t, t, ss);
    c = uv.z + sw.z; c = (c >= 0.f) ? c : a * c; t = fmaf(g, c, hh.z); o.z = t; ss = fmaf(t, t, ss);
    c = uv.w + sw.w; c = (c >= 0.f) ? c : a * c; t = fmaf(g, c, hh.w); o.w = t; ss = fmaf(t, t, ss);
}

// ---------------------------------------------------------------------------
// Mega kernel, one launch, three roles by blockIdx.x (producers first):
//  [0,320):      GEMM (R3 measured-best body) -> g_sW / g_gate; flags g_flag_w
//  [320,2368):   UV (warp per element) -> g_UV; flags g_flag_uv[n/16]
//  [2368,3392):  k3 (R2 measured-best body); spins on its tile's flags with
//                VOLATILE loads + nanosleep backoff (no atomic spin storm).
// Deadlock-free: producers have lower blockIdx and never wait.
// ---------------------------------------------------------------------------
__global__ void __launch_bounds__(256) mega(
    const float* __restrict__ s, const float* __restrict__ W,
    const float* __restrict__ h, const float* __restrict__ w,
    const float* __restrict__ U, const float* __restrict__ V,
    const float* __restrict__ a_ptr, float* __restrict__ out)
{
    __shared__ union {
        struct { float sa[32][64]; float sb[32][64]; } g;      // 16 KiB
        struct { float4 sw[2][64]; float gt[2][16]; } c;       //  2.2 KiB
    } sm;

    const int tid = threadIdx.x;
    const int blk = blockIdx.x;

    if (blk < NB_GEMM) {
        // ================= GEMM =================
        const int mx = blk % 5;
        const int b0 = (blk / 5) * 64;
        const int m0 = mx * 64;
        const bool gate_tile = (mx == 4);
        const int row = tid & 63;
        const int kq = (tid >> 6) << 2;
        const int tx = tid & 15;
        const int ty = tid >> 4;
        const int rb = ty << 2;
        const int cm = tx << 2;

        u64 acc2[2][4] = {};

        float4 ra0, ra1, rb0, rb1;
        ra0 = *(const float4*)&s[(b0 + row) * H_ + kq];
        ra1 = *(const float4*)&s[(b0 + row) * H_ + 16 + kq];
        if (!gate_tile) {
            rb0 = *(const float4*)&W[(m0 + row) * H_ + kq];
            rb1 = *(const float4*)&W[(m0 + row) * H_ + 16 + kq];
        } else {
            float4 x0 = *(const float4*)&h[row * H_ + kq];
            float4 x1 = *(const float4*)&h[row * H_ + 16 + kq];
            float4 y0 = *(const float4*)&w[row * H_ + kq];
            float4 y1 = *(const float4*)&w[row * H_ + 16 + kq];
            rb0 = make_float4(x0.x + y0.x, x0.y + y0.y, x0.z + y0.z, x0.w + y0.w);
            rb1 = make_float4(x1.x + y1.x, x1.y + y1.y, x1.z + y1.z, x1.w + y1.w);
        }

        for (int kc = 0; kc < H_; kc += 32) {
            sm.g.sa[kq + 0][row] = ra0.x; sm.g.sa[kq + 1][row] = ra0.y;
            sm.g.sa[kq + 2][row] = ra0.z; sm.g.sa[kq + 3][row] = ra0.w;
            sm.g.sa[16 + kq + 0][row] = ra1.x; sm.g.sa[16 + kq + 1][row] = ra1.y;
            sm.g.sa[16 + kq + 2][row] = ra1.z; sm.g.sa[16 + kq + 3][row] = ra1.w;
            sm.g.sb[kq + 0][row] = rb0.x; sm.g.sb[kq + 1][row] = rb0.y;
            sm.g.sb[kq + 2][row] = rb0.z; sm.g.sb[kq + 3][row] = rb0.w;
            sm.g.sb[16 + kq + 0][row] = rb1.x; sm.g.sb[16 + kq + 1][row] = rb1.y;
            sm.g.sb[16 + kq + 2][row] = rb1.z; sm.g.sb[16 + kq + 3][row] = rb1.w;
            __syncthreads();

            if (kc + 32 < H_) {
                const int kn = kc + 32;
                ra0 = *(const float4*)&s[(b0 + row) * H_ + kn + kq];
                ra1 = *(const float4*)&s[(b0 + row) * H_ + kn + 16 + kq];
                if (!gate_tile) {
                    rb0 = *(const float4*)&W[(m0 + row) * H_ + kn + kq];
                    rb1 = *(const float4*)&W[(m0 + row) * H_ + kn + 16 + kq];
                } else {
                    float4 x0 = *(const float4*)&h[row * H_ + kn + kq];
                    float4 x1 = *(const float4*)&h[row * H_ + kn + 16 + kq];
                    float4 y0 = *(const float4*)&w[row * H_ + kn + kq];
                    float4 y1 = *(const float4*)&w[row * H_ + kn + 16 + kq];
                    rb0 = make_float4(x0.x + y0.x, x0.y + y0.y, x0.z + y0.z, x0.w + y0.w);
                    rb1 = make_float4(x1.x + y1.x, x1.y + y1.y, x1.z + y1.z, x1.w + y1.w);
                }
            }

#pragma unroll 8
            for (int k = 0; k < 32; ++k) {
                const ulonglong2 a2 = *(const ulonglong2*)&sm.g.sa[k][rb];
                const float4 bv = *(const float4*)&sm.g.sb[k][cm];
                u64 bx = pack2(bv.x, bv.x);
                u64 by = pack2(bv.y, bv.y);
                u64 bz = pack2(bv.z, bv.z);
                u64 bw = pack2(bv.w, bv.w);
                acc2[0][0] = fma2(a2.x, bx, acc2[0][0]);
                acc2[0][1] = fma2(a2.x, by, acc2[0][1]);
                acc2[0][2] = fma2(a2.x, bz, acc2[0][2]);
                acc2[0][3] = fma2(a2.x, bw, acc2[0][3]);
                acc2[1][0] = fma2(a2.y, bx, acc2[1][0]);
                acc2[1][1] = fma2(a2.y, by, acc2[1][1]);
                acc2[1][2] = fma2(a2.y, bz, acc2[1][2]);
                acc2[1][3] = fma2(a2.y, bw, acc2[1][3]);
            }
            __syncthreads();
        }

#pragma unroll
        for (int ib = 0; ib < 2; ++ib) {
            float2 c0 = unpack2(acc2[ib][0]);
            float2 c1 = unpack2(acc2[ib][1]);
            float2 c2 = unpack2(acc2[ib][2]);
            float2 c3 = unpack2(acc2[ib][3]);
            const int bA = b0 + rb + 2 * ib;
            if (!gate_tile) {
                *(float4*)&g_sW[bA * H_ + m0 + cm] = make_float4(c0.x, c1.x, c2.x, c3.x);
                *(float4*)&g_sW[(bA + 1) * H_ + m0 + cm] = make_float4(c0.y, c1.y, c2.y, c3.y);
            } else {
                *(float4*)&g_gate[bA * N_ + cm] = make_float4(
                    1.0f / (1.0f + __expf(-c0.x)), 1.0f / (1.0f + __expf(-c1.x)),
                    1.0f / (1.0f + __expf(-c2.x)), 1.0f / (1.0f + __expf(-c3.x)));
                *(float4*)&g_gate[(bA + 1) * N_ + cm] = make_float4(
                    1.0f / (1.0f + __expf(-c0.y)), 1.0f / (1.0f + __expf(-c1.y)),
                    1.0f / (1.0f + __expf(-c2.y)), 1.0f / (1.0f + __expf(-c3.y)));
            }
        }
        __threadfence();
        __syncthreads();
        if (tid == 0) atomicAdd(&g_flag_w[blk / 5], 1);

    } else if (blk < NB_GEMM + NB_UV) {
        // ================= UV =================
        const int id = blk - NB_GEMM;
        const int n = id >> 5;
        const int kg = id & 31;
        const int warp = tid >> 5;
        const int lane = tid & 31;
        const int k = kg * 8 + warp;
        const int off = lane * 8;

        const float4* u4 = (const float4*)(U + k * H_ + off);
        const float4* v4 = (const float4*)(V + k * H_ + off);
        const float4* h4 = (const float4*)(h + n * H_ + off);
        const float4* w4 = (const float4*)(w + n * H_ + off);
        float4 u0 = u4[0], u1 = u4[1];
        float4 v0 = v4[0], v1 = v4[1];
        float4 x0 = __ldg(h4), x1 = __ldg(h4 + 1);
        float4 y0 = __ldg(w4), y1 = __ldg(w4 + 1);

        float acc = 0.f;
        acc = fmaf(u0.x, x0.x, acc); acc = fmaf(u0.y, x0.y, acc);
        acc = fmaf(u0.z, x0.z, acc); acc = fmaf(u0.w, x0.w, acc);
        acc = fmaf(u1.x, x1.x, acc); acc = fmaf(u1.y, x1.y, acc);
        acc = fmaf(u1.z, x1.z, acc); acc = fmaf(u1.w, x1.w, acc);
        acc = fmaf(v0.x, y0.x, acc); acc = fmaf(v0.y, y0.y, acc);
        acc = fmaf(v0.z, y0.z, acc); acc = fmaf(v0.w, y0.w, acc);
        acc = fmaf(v1.x, y1.x, acc); acc = fmaf(v1.y, y1.y, acc);
        acc = fmaf(v1.z, y1.z, acc); acc = fmaf(v1.w, y1.w, acc);

#pragma unroll
        for (int o = 16; o > 0; o >>= 1)
            acc += __shfl_xor_sync(0xFFFFFFFFu, acc, o);
        if (lane == 0) g_UV[n * H_ + k] = acc;

        __threadfence();
        __syncthreads();
        if (tid == 0) atomicAdd(&g_flag_uv[n >> 4], 1);

    } else {
        // ================= k3 (consumer, R2 body) =================
        const int id = blk - (NB_GEMM + NB_UV);
        const int n0 = (id & 3) * 16;
        const int b0 = (id >> 2) * TB3;
        const int bt = b0 >> 6;

        const int warp = tid >> 5;
        const int lane = tid & 31;
        const int nA = n0 + warp;
        const int nB = n0 + warp + 8;
        const int k0 = lane * 4;
        const int k1 = 128 + lane * 4;

        // Pure inputs: load before waiting (overlaps the spin).
        float4 hA0 = __ldg((const float4*)&h[nA * H_ + k0]);
        float4 hA1 = __ldg((const float4*)&h[nA * H_ + k1]);
        float4 hB0 = __ldg((const float4*)&h[nB * H_ + k0]);
        float4 hB1 = __ldg((const float4*)&h[nB * H_ + k1]);
        const float a = __ldg(a_ptr);

        // VOLATILE-load spin with backoff (no atomics -> no L2 ALU storm).
        if (tid == 0) {
            while (((volatile int*)g_flag_w)[bt] < 5) __nanosleep(256);
            while (((volatile int*)g_flag_uv)[n0 >> 4] < 512) __nanosleep(256);
            __threadfence();
        }
        __syncthreads();

        float4 uvA0 = *(const float4*)&g_UV[nA * H_ + k0];
        float4 uvA1 = *(const float4*)&g_UV[nA * H_ + k1];
        float4 uvB0 = *(const float4*)&g_UV[nB * H_ + k0];
        float4 uvB1 = *(const float4*)&g_UV[nB * H_ + k1];

        if (tid < 64) sm.c.sw[0][tid] = __ldg((const float4*)&g_sW[(size_t)b0 * H_] + tid);
        else if (tid < 80) sm.c.gt[0][tid - 64] = __ldg(&g_gate[b0 * N_ + n0 + (tid - 64)]);
        __syncthreads();

        for (int i = 0; i < TB3; ++i) {
            const int buf = i & 1;
            if (i + 1 < TB3) {
                const int bn = b0 + i + 1;
                if (tid < 64) sm.c.sw[buf ^ 1][tid] = __ldg((const float4*)&g_sW[(size_t)bn * H_] + tid);
                else if (tid < 80) sm.c.gt[buf ^ 1][tid - 64] = __ldg(&g_gate[bn * N_ + n0 + (tid - 64)]);
            }

            const float4 s0 = sm.c.sw[buf][lane];
            const float4 s1 = sm.c.sw[buf][lane + 32];
            const float gA = sm.c.gt[buf][warp];
            const float gB = sm.c.gt[buf][warp + 8];

            float4 oA0, oA1, oB0, oB1;
            float ssA = 0.f, ssB = 0.f;
            row_step(uvA0, hA0, s0, gA, a, oA0, ssA);
            row_step(uvA1, hA1, s1, gA, a, oA1, ssA);
            row_step(uvB0, hB0, s0, gB, a, oB0, ssB);
            row_step(uvB1, hB1, s1, gB, a, oB1, ssB);

#pragma unroll
            for (int o = 16; o > 0; o >>= 1) {
                ssA += __shfl_xor_sync(0xFFFFFFFFu, ssA, o);
                ssB += __shfl_xor_sync(0xFFFFFFFFu, ssB, o);
            }
            const float iA = rsqrtf(ssA);
            const float iB = rsqrtf(ssB);

            const int b = b0 + i;
            float4* oA = (float4*)&out[((size_t)b * N_ + nA) * H_];
            float4* oB = (float4*)&out[((size_t)b * N_ + nB) * H_];
            oA[lane]      = make_float4(oA0.x * iA, oA0.y * iA, oA0.z * iA, oA0.w * iA);
            oA[32 + lane] = make_float4(oA1.x * iA, oA1.y * iA, oA1.z * iA, oA1.w * iA);
            oB[lane]      = make_float4(oB0.x * iB, oB0.y * iB, oB0.z * iB, oB0.w * iB);
            oB[32 + lane] = make_float4(oB1.x * iB, oB1.y * iB, oB1.z * iB, oB1.w * iB);

            __syncthreads();
        }
    }
}

// ---------------------------------------------------------------------------
extern "C" void kernel_launch(void* const* d_in, const int* in_sizes, int n_in,
                              void* d_out, int out_size)
{
    const float* s_t = (const float*)d_in[0];   // [B,H]
    const float* h   = (const float*)d_in[1];   // [1,N,H]
    const float* w   = (const float*)d_in[2];   // [1,N,H]
    const float* U   = (const float*)d_in[3];   // [H,H]
    const float* V   = (const float*)d_in[4];   // [H,H]
    const float* W   = (const float*)d_in[5];   // [H,H]
    const float* pa  = (const float*)d_in[6];   // [1]
    float* out = (float*)d_out;                 // [B,N,H]

    k_reset<<<1, 128>>>();
    mega<<<NB_GEMM + NB_UV + NB_K3, 256>>>(s_t, W, h, w, U, V, pa, out);
}